// round 14
// baseline (speedup 1.0000x reference)
#include <cuda_runtime.h>
#include <cuda_bf16.h>
#include <cstdint>

// ---------------------------------------------------------------------------
// out[8192,4096] = heaviside( (x/(||x||+1e-4)) @ W^T - 1 )
//
// Certified shortcut: ||x_norm|| = ||x||/(||x||+1e-4) < 1 strictly for all x;
// if max_j ||W_j||^2 < 0.96 then |h| < 0.98 < 1 everywhere and the output is
// identically zero. Certificate computed on-device every call (pure function
// of inputs -> deterministic, graph-safe).
//
// K1 (8192 uniform blocks, 24KB contiguous bursts): cert + zero-fill, and
//     resets the fallback grid barrier counter.
// K2 (fallback only, 296 CTAs = one resident wave): prep (x-norm->bf16,
//     W->bf16) -> software grid barrier -> persistent mma.sync GEMM + spike.
//     Early-exits before the barrier when the certificate holds.
//
// R14: both kernels pinned to the same max-shared carveout so graph replay
//      doesn't toggle the SM L1/shared split between K1 (32B smem) and K2
//      (96KB smem) every iteration.
// ---------------------------------------------------------------------------

#define BDIM   8192
#define INDIM  4096
#define OUTDIM 4096

#define CERT_BOUND 0.96f
#define NROWBLK OUTDIM                 // 4096 W rows
#define NB1 8192                       // K1 blocks (uniform 24KB work each)

__device__ __align__(16) unsigned char g_rowbad[NROWBLK];   // 1 byte per W row
__device__ unsigned int g_bar;                              // fallback barrier
__device__ __nv_bfloat16 g_xb[(size_t)BDIM * INDIM];        // 64 MB
__device__ __nv_bfloat16 g_wb[(size_t)OUTDIM * INDIM];      // 32 MB

// ---------------------------------------------------------------------------
// helpers
// ---------------------------------------------------------------------------
__device__ __forceinline__ uint32_t smem_u32(const void* p) {
    uint32_t a;
    asm("{ .reg .u64 t; cvta.to.shared.u64 t, %1; cvt.u32.u64 %0, t; }"
        : "=r"(a) : "l"(p));
    return a;
}

#define CPA16(dst, src) \
    asm volatile("cp.async.cg.shared.global [%0], [%1], 16;" :: "r"(dst), "l"(src))

__device__ __forceinline__ void ldsm_x4(uint32_t& r0, uint32_t& r1, uint32_t& r2,
                                        uint32_t& r3, uint32_t addr) {
    asm volatile("ldmatrix.sync.aligned.m8n8.x4.shared.b16 {%0,%1,%2,%3}, [%4];"
                 : "=r"(r0), "=r"(r1), "=r"(r2), "=r"(r3) : "r"(addr));
}

__device__ __forceinline__ void mma16816(float* c, const uint32_t* a,
                                         uint32_t b0, uint32_t b1) {
    asm volatile(
        "mma.sync.aligned.m16n8k16.row.col.f32.bf16.bf16.f32 "
        "{%0,%1,%2,%3}, {%4,%5,%6,%7}, {%8,%9}, {%0,%1,%2,%3};"
        : "+f"(c[0]), "+f"(c[1]), "+f"(c[2]), "+f"(c[3])
        : "r"(a[0]), "r"(a[1]), "r"(a[2]), "r"(a[3]), "r"(b0), "r"(b1));
}

__device__ __forceinline__ uint2 pack_bf16x4(float4 v, float sc) {
    __nv_bfloat162 lo = __floats2bfloat162_rn(v.x * sc, v.y * sc);
    __nv_bfloat162 hi = __floats2bfloat162_rn(v.z * sc, v.w * sc);
    uint2 r;
    r.x = *reinterpret_cast<unsigned*>(&lo);
    r.y = *reinterpret_cast<unsigned*>(&hi);
    return r;
}

// certificate check: 4096 flag bytes = 256 threads x one uint4 each
__device__ __forceinline__ int cert_failed(int t) {
    const uint4* p = reinterpret_cast<const uint4*>(g_rowbad);
    uint4 v = p[t];
    int pred = (v.x | v.y | v.z | v.w) != 0u;
    return __syncthreads_or(pred);
}

// ---------------------------------------------------------------------------
// K1: uniform-burst certificate + zero-fill (24KB per block) + barrier reset
// ---------------------------------------------------------------------------
__global__ void __launch_bounds__(256) check_zero_kernel(const float* __restrict__ W,
                                                         float* __restrict__ out) {
    const int b = blockIdx.x;
    const int t = threadIdx.x;
    const float4 z = make_float4(0.0f, 0.0f, 0.0f, 0.0f);
    float4* o4 = reinterpret_cast<float4*>(out);

    if (b == 0 && t == 0) g_bar = 0;     // reset fallback grid barrier

    if (b < NROWBLK) {
        // read W row b: 1024 float4, 4 per thread (contiguous, coalesced)
        const float4* wr = reinterpret_cast<const float4*>(W) + (size_t)b * (INDIM / 4);
        float4 v0 = wr[t], v1 = wr[t + 256], v2 = wr[t + 512], v3 = wr[t + 768];

        // zero 8KB slice: out[0 .. 32MB) region, block b -> 512 float4
        float4* zb = o4 + (size_t)b * 512;
        zb[t] = z;
        zb[t + 256] = z;

        float ss = v0.x*v0.x + v0.y*v0.y + v0.z*v0.z + v0.w*v0.w
                 + v1.x*v1.x + v1.y*v1.y + v1.z*v1.z + v1.w*v1.w
                 + v2.x*v2.x + v2.y*v2.y + v2.z*v2.z + v2.w*v2.w
                 + v3.x*v3.x + v3.y*v3.y + v3.z*v3.z + v3.w*v3.w;
        #pragma unroll
        for (int o = 16; o > 0; o >>= 1)
            ss += __shfl_xor_sync(0xFFFFFFFFu, ss, o);
        __shared__ float ws[8];
        if ((t & 31) == 0) ws[t >> 5] = ss;
        __syncthreads();
        if (t == 0) {
            float tot = ws[0] + ws[1] + ws[2] + ws[3] + ws[4] + ws[5] + ws[6] + ws[7];
            g_rowbad[b] = (tot >= CERT_BOUND) ? 1u : 0u;
        }
    } else {
        // zero 24KB slice: out[32MB ..) region, 1536 float4 per block
        float4* zb = o4 + (size_t)(2 * 1024 * 1024) + (size_t)(b - NROWBLK) * 1536;
        #pragma unroll
        for (int j = 0; j < 6; j++)
            zb[t + j * 256] = z;
    }
}

// ---------------------------------------------------------------------------
// K2: merged fallback — prep + grid barrier + persistent GEMM + spike.
//   296 CTAs, 2/SM, all co-resident (barrier is deadlock-free).
//   Early-exits (before barrier) when the certificate holds.
// ---------------------------------------------------------------------------
#define BM 128
#define BN 128
#define BK 64
#define NKITERS (INDIM / BK)       // 64
#define TILE_BYTES 16384
#define STAGE_BYTES (2 * TILE_BYTES)
#define NSTAGES 3
#define SMEM_DYN (NSTAGES * STAGE_BYTES)
#define NTILES ((BDIM / BM) * (OUTDIM / BN))  // 2048
#define GBLK 296

__device__ __forceinline__ uint32_t sw_off(int row, int chunk) {
    return (uint32_t)(row * 128 + ((chunk ^ (row & 7)) << 4));
}

__global__ void __launch_bounds__(256, 2) fallback_kernel(const float* __restrict__ x,
                                                          const float* __restrict__ W,
                                                          float* __restrict__ out) {
    const int t = threadIdx.x;
    if (!cert_failed(t)) return;          // certified fast path: done

    extern __shared__ unsigned char smem_raw[];
    uint32_t smem_base = smem_u32(smem_raw);
    const int wid = t >> 5, lane = t & 31;

    // ---- phase 1: prep (grid-stride over x rows, then W convert) ----
    {
        __shared__ float ws[8];
        for (int row = blockIdx.x; row < BDIM; row += GBLK) {
            const float4* xr = reinterpret_cast<const float4*>(x)
                             + (size_t)row * (INDIM / 4);
            float4 v0 = xr[t], v1 = xr[t + 256], v2 = xr[t + 512], v3 = xr[t + 768];
            float ss = v0.x*v0.x + v0.y*v0.y + v0.z*v0.z + v0.w*v0.w
                     + v1.x*v1.x + v1.y*v1.y + v1.z*v1.z + v1.w*v1.w
                     + v2.x*v2.x + v2.y*v2.y + v2.z*v2.z + v2.w*v2.w
                     + v3.x*v3.x + v3.y*v3.y + v3.z*v3.z + v3.w*v3.w;
            #pragma unroll
            for (int o = 16; o > 0; o >>= 1)
                ss += __shfl_xor_sync(0xFFFFFFFFu, ss, o);
            if ((t & 31) == 0) ws[t >> 5] = ss;
            __syncthreads();
            float tot = ws[0] + ws[1] + ws[2] + ws[3] + ws[4] + ws[5] + ws[6] + ws[7];
            float sc = 1.0f / (sqrtf(tot) + 1e-4f);
            uint2* o2 = reinterpret_cast<uint2*>(g_xb + (size_t)row * INDIM);
            o2[t]       = pack_bf16x4(v0, sc);
            o2[t + 256] = pack_bf16x4(v1, sc);
            o2[t + 512] = pack_bf16x4(v2, sc);
            o2[t + 768] = pack_bf16x4(v3, sc);
            __syncthreads();
        }
        const size_t n4 = (size_t)OUTDIM * INDIM / 4;
        const float4* w4 = reinterpret_cast<const float4*>(W);
        uint2* o2 = reinterpret_cast<uint2*>(g_wb);
        size_t stride = (size_t)GBLK * 256;
        for (size_t i = (size_t)blockIdx.x * 256 + t; i < n4; i += stride) {
            float4 v = w4[i];
            o2[i] = pack_bf16x4(v, 1.0f);
        }
    }

    // ---- grid barrier (all 296 CTAs co-resident; counter reset by K1) ----
    __threadfence();
    __syncthreads();
    if (t == 0) {
        atomicAdd(&g_bar, 1u);
        while (*(volatile unsigned int*)&g_bar < (unsigned)GBLK) { }
    }
    __syncthreads();
    __threadfence();

    // ---- phase 2: persistent GEMM + spike epilogue ----
    const int warp_m = wid >> 2, warp_n = wid & 3;
    const int lrow = t >> 1, lhalf = (t & 1) * 4;
    const int a_row = warp_m * 64 + (lane & 15);
    const int a_csel = lane >> 4;
    const int b_row = warp_n * 32 + (lane & 7) + ((lane >> 4) << 3);
    const int b_csel = (lane >> 3) & 1;

    for (int tile = blockIdx.x; tile < NTILES; tile += GBLK) {
        const int NUM_N = OUTDIM / BN;    // 32
        const int GROUP = 8;
        int per_g = GROUP * NUM_N;
        int g = tile / per_g;
        int rem = tile - g * per_g;
        const size_t m0 = (size_t)(g * GROUP + (rem & (GROUP - 1))) * BM;
        const size_t n0 = (size_t)(rem / GROUP) * BN;

        auto load_stage = [&](int it) {
            uint32_t base = smem_base + (uint32_t)(it % NSTAGES) * STAGE_BYTES;
            const char* as = (const char*)(g_xb + (m0 + (size_t)lrow) * INDIM
                                           + (size_t)it * BK) + lhalf * 16;
            const char* bs = (const char*)(g_wb + (n0 + (size_t)lrow) * INDIM
                                           + (size_t)it * BK) + lhalf * 16;
            #pragma unroll
            for (int c = 0; c < 4; c++) {
                CPA16(base + sw_off(lrow, lhalf + c), as + c * 16);
                CPA16(base + TILE_BYTES + sw_off(lrow, lhalf + c), bs + c * 16);
            }
        };

        load_stage(0); asm volatile("cp.async.commit_group;");
        load_stage(1); asm volatile("cp.async.commit_group;");

        float acc[4][4][4];
        #pragma unroll
        for (int i = 0; i < 4; i++)
            #pragma unroll
            for (int j = 0; j < 4; j++)
                #pragma unroll
                for (int q = 0; q < 4; q++) acc[i][j][q] = 0.0f;

        for (int i = 0; i < NKITERS; i++) {
            asm volatile("cp.async.wait_group 1;");
            __syncthreads();

            if (i + 2 < NKITERS) load_stage(i + 2);
            asm volatile("cp.async.commit_group;");

            uint32_t abase = smem_base + (uint32_t)(i % NSTAGES) * STAGE_BYTES;
            uint32_t bbase = abase + TILE_BYTES;

            #pragma unroll
            for (int ks = 0; ks < 4; ks++) {
                const int kc = ks * 2;
                uint32_t a[4][4];
                #pragma unroll
                for (int mf = 0; mf < 4; mf++) {
                    int r = a_row + mf * 16;
                    ldsm_x4(a[mf][0], a[mf][1], a[mf][2], a[mf][3],
                            abase + sw_off(r, kc + a_csel));
                }
                uint32_t b[2][4];
                #pragma unroll
                for (int bf = 0; bf < 2; bf++) {
                    int r = b_row + bf * 16;
                    ldsm_x4(b[bf][0], b[bf][1], b[bf][2], b[bf][3],
                            bbase + sw_off(r, kc + b_csel));
                }
                #pragma unroll
                for (int mf = 0; mf < 4; mf++) {
                    #pragma unroll
                    for (int bf = 0; bf < 2; bf++) {
                        mma16816(acc[mf][bf * 2 + 0], a[mf], b[bf][0], b[bf][1]);
                        mma16816(acc[mf][bf * 2 + 1], a[mf], b[bf][2], b[bf][3]);
                    }
                }
            }
            __syncthreads();
        }

        #pragma unroll
        for (int mf = 0; mf < 4; mf++) {
            size_t row = m0 + (size_t)(warp_m * 64 + mf * 16 + (lane >> 2));
            #pragma unroll
            for (int nf = 0; nf < 4; nf++) {
                size_t col = n0 + (size_t)(warp_n * 32 + nf * 8 + (lane & 3) * 2);
                float2 v0, v1;
                v0.x = (acc[mf][nf][0] >= 1.0f) ? 1.0f : 0.0f;
                v0.y = (acc[mf][nf][1] >= 1.0f) ? 1.0f : 0.0f;
                v1.x = (acc[mf][nf][2] >= 1.0f) ? 1.0f : 0.0f;
                v1.y = (acc[mf][nf][3] >= 1.0f) ? 1.0f : 0.0f;
                *reinterpret_cast<float2*>(out + row * OUTDIM + col) = v0;
                *reinterpret_cast<float2*>(out + (row + 8) * OUTDIM + col) = v1;
            }
        }
        __syncthreads();
    }
}

// ---------------------------------------------------------------------------
// Launch: 2 static launches; both kernels pinned to max-shared carveout so
// graph replay doesn't toggle the SM L1/shared split every iteration.
// ---------------------------------------------------------------------------
extern "C" void kernel_launch(void* const* d_in, const int* in_sizes, int n_in,
                              void* d_out, int out_size) {
    const float* x = (const float*)d_in[0];
    const float* W = (const float*)d_in[1];
    float* out = (float*)d_out;

    static int configured = 0;
    if (!configured) {
        cudaFuncSetAttribute(fallback_kernel,
                             cudaFuncAttributeMaxDynamicSharedMemorySize, SMEM_DYN);
        cudaFuncSetAttribute(fallback_kernel,
                             cudaFuncAttributePreferredSharedMemoryCarveout, 100);
        cudaFuncSetAttribute(check_zero_kernel,
                             cudaFuncAttributePreferredSharedMemoryCarveout, 100);
        configured = 1;
    }

    check_zero_kernel<<<NB1, 256>>>(W, out);               // cert + zero-fill
    fallback_kernel<<<GBLK, 256, SMEM_DYN>>>(x, W, out);   // fallback only
}

// round 15
// speedup vs baseline: 1.0716x; 1.0716x over previous
#include <cuda_runtime.h>
#include <cuda_bf16.h>
#include <cstdint>

// ---------------------------------------------------------------------------
// out[8192,4096] = heaviside( (x/(||x||+1e-4)) @ W^T - 1 )
//
// Certified shortcut: ||x_norm|| = ||x||/(||x||+1e-4) < 1 strictly for all x;
// if max_j ||W_j||^2 < 0.96 then |h| < 0.98 < 1 everywhere and the output is
// identically zero. Certificate computed on-device every call (pure function
// of inputs -> deterministic, graph-safe).
//
// K1 (8192 uniform blocks, 24KB contiguous bursts): cert + zero-fill, and
//     resets the fallback grid barrier counter. Default L1 carveout (R14
//     showed pinning carveout=100 hurts K1's streaming bursts).
// K2 (fallback only, 296 CTAs): prep -> grid barrier -> persistent mma.sync
//     GEMM + spike. Early-exits before the barrier when the cert holds.
//     R15: 2-stage pipeline (64KB smem, was 96KB) to probe whether the
//     4.2us early-exit dispatch cost scales with per-CTA smem reservation.
// ---------------------------------------------------------------------------

#define BDIM   8192
#define INDIM  4096
#define OUTDIM 4096

#define CERT_BOUND 0.96f
#define NROWBLK OUTDIM                 // 4096 W rows
#define NB1 8192                       // K1 blocks (uniform 24KB work each)

__device__ __align__(16) unsigned char g_rowbad[NROWBLK];   // 1 byte per W row
__device__ unsigned int g_bar;                              // fallback barrier
__device__ __nv_bfloat16 g_xb[(size_t)BDIM * INDIM];        // 64 MB
__device__ __nv_bfloat16 g_wb[(size_t)OUTDIM * INDIM];      // 32 MB

// ---------------------------------------------------------------------------
// helpers
// ---------------------------------------------------------------------------
__device__ __forceinline__ uint32_t smem_u32(const void* p) {
    uint32_t a;
    asm("{ .reg .u64 t; cvta.to.shared.u64 t, %1; cvt.u32.u64 %0, t; }"
        : "=r"(a) : "l"(p));
    return a;
}

#define CPA16(dst, src) \
    asm volatile("cp.async.cg.shared.global [%0], [%1], 16;" :: "r"(dst), "l"(src))

__device__ __forceinline__ void ldsm_x4(uint32_t& r0, uint32_t& r1, uint32_t& r2,
                                        uint32_t& r3, uint32_t addr) {
    asm volatile("ldmatrix.sync.aligned.m8n8.x4.shared.b16 {%0,%1,%2,%3}, [%4];"
                 : "=r"(r0), "=r"(r1), "=r"(r2), "=r"(r3) : "r"(addr));
}

__device__ __forceinline__ void mma16816(float* c, const uint32_t* a,
                                         uint32_t b0, uint32_t b1) {
    asm volatile(
        "mma.sync.aligned.m16n8k16.row.col.f32.bf16.bf16.f32 "
        "{%0,%1,%2,%3}, {%4,%5,%6,%7}, {%8,%9}, {%0,%1,%2,%3};"
        : "+f"(c[0]), "+f"(c[1]), "+f"(c[2]), "+f"(c[3])
        : "r"(a[0]), "r"(a[1]), "r"(a[2]), "r"(a[3]), "r"(b0), "r"(b1));
}

__device__ __forceinline__ uint2 pack_bf16x4(float4 v, float sc) {
    __nv_bfloat162 lo = __floats2bfloat162_rn(v.x * sc, v.y * sc);
    __nv_bfloat162 hi = __floats2bfloat162_rn(v.z * sc, v.w * sc);
    uint2 r;
    r.x = *reinterpret_cast<unsigned*>(&lo);
    r.y = *reinterpret_cast<unsigned*>(&hi);
    return r;
}

// certificate check: 4096 flag bytes = 256 threads x one uint4 each
__device__ __forceinline__ int cert_failed(int t) {
    const uint4* p = reinterpret_cast<const uint4*>(g_rowbad);
    uint4 v = p[t];
    int pred = (v.x | v.y | v.z | v.w) != 0u;
    return __syncthreads_or(pred);
}

// ---------------------------------------------------------------------------
// K1: uniform-burst certificate + zero-fill (24KB per block) + barrier reset
// ---------------------------------------------------------------------------
__global__ void __launch_bounds__(256) check_zero_kernel(const float* __restrict__ W,
                                                         float* __restrict__ out) {
    const int b = blockIdx.x;
    const int t = threadIdx.x;
    const float4 z = make_float4(0.0f, 0.0f, 0.0f, 0.0f);
    float4* o4 = reinterpret_cast<float4*>(out);

    if (b == 0 && t == 0) g_bar = 0;     // reset fallback grid barrier

    if (b < NROWBLK) {
        // read W row b: 1024 float4, 4 per thread (contiguous, coalesced)
        const float4* wr = reinterpret_cast<const float4*>(W) + (size_t)b * (INDIM / 4);
        float4 v0 = wr[t], v1 = wr[t + 256], v2 = wr[t + 512], v3 = wr[t + 768];

        // zero 8KB slice: out[0 .. 32MB) region, block b -> 512 float4
        float4* zb = o4 + (size_t)b * 512;
        zb[t] = z;
        zb[t + 256] = z;

        float ss = v0.x*v0.x + v0.y*v0.y + v0.z*v0.z + v0.w*v0.w
                 + v1.x*v1.x + v1.y*v1.y + v1.z*v1.z + v1.w*v1.w
                 + v2.x*v2.x + v2.y*v2.y + v2.z*v2.z + v2.w*v2.w
                 + v3.x*v3.x + v3.y*v3.y + v3.z*v3.z + v3.w*v3.w;
        #pragma unroll
        for (int o = 16; o > 0; o >>= 1)
            ss += __shfl_xor_sync(0xFFFFFFFFu, ss, o);
        __shared__ float ws[8];
        if ((t & 31) == 0) ws[t >> 5] = ss;
        __syncthreads();
        if (t == 0) {
            float tot = ws[0] + ws[1] + ws[2] + ws[3] + ws[4] + ws[5] + ws[6] + ws[7];
            g_rowbad[b] = (tot >= CERT_BOUND) ? 1u : 0u;
        }
    } else {
        // zero 24KB slice: out[32MB ..) region, 1536 float4 per block
        float4* zb = o4 + (size_t)(2 * 1024 * 1024) + (size_t)(b - NROWBLK) * 1536;
        #pragma unroll
        for (int j = 0; j < 6; j++)
            zb[t + j * 256] = z;
    }
}

// ---------------------------------------------------------------------------
// K2: merged fallback — prep + grid barrier + persistent GEMM + spike.
//   296 CTAs co-resident (2/SM even at 64KB smem). 2-stage pipeline.
//   Early-exits (before barrier) when the certificate holds.
// ---------------------------------------------------------------------------
#define BM 128
#define BN 128
#define BK 64
#define NKITERS (INDIM / BK)       // 64
#define TILE_BYTES 16384
#define STAGE_BYTES (2 * TILE_BYTES)
#define NSTAGES 2
#define SMEM_DYN (NSTAGES * STAGE_BYTES)   // 64 KB
#define NTILES ((BDIM / BM) * (OUTDIM / BN))  // 2048
#define GBLK 296

__device__ __forceinline__ uint32_t sw_off(int row, int chunk) {
    return (uint32_t)(row * 128 + ((chunk ^ (row & 7)) << 4));
}

__global__ void __launch_bounds__(256, 2) fallback_kernel(const float* __restrict__ x,
                                                          const float* __restrict__ W,
                                                          float* __restrict__ out) {
    const int t = threadIdx.x;
    if (!cert_failed(t)) return;          // certified fast path: done

    extern __shared__ unsigned char smem_raw[];
    uint32_t smem_base = smem_u32(smem_raw);
    const int wid = t >> 5, lane = t & 31;

    // ---- phase 1: prep (grid-stride over x rows, then W convert) ----
    {
        __shared__ float ws[8];
        for (int row = blockIdx.x; row < BDIM; row += GBLK) {
            const float4* xr = reinterpret_cast<const float4*>(x)
                             + (size_t)row * (INDIM / 4);
            float4 v0 = xr[t], v1 = xr[t + 256], v2 = xr[t + 512], v3 = xr[t + 768];
            float ss = v0.x*v0.x + v0.y*v0.y + v0.z*v0.z + v0.w*v0.w
                     + v1.x*v1.x + v1.y*v1.y + v1.z*v1.z + v1.w*v1.w
                     + v2.x*v2.x + v2.y*v2.y + v2.z*v2.z + v2.w*v2.w
                     + v3.x*v3.x + v3.y*v3.y + v3.z*v3.z + v3.w*v3.w;
            #pragma unroll
            for (int o = 16; o > 0; o >>= 1)
                ss += __shfl_xor_sync(0xFFFFFFFFu, ss, o);
            if ((t & 31) == 0) ws[t >> 5] = ss;
            __syncthreads();
            float tot = ws[0] + ws[1] + ws[2] + ws[3] + ws[4] + ws[5] + ws[6] + ws[7];
            float sc = 1.0f / (sqrtf(tot) + 1e-4f);
            uint2* o2 = reinterpret_cast<uint2*>(g_xb + (size_t)row * INDIM);
            o2[t]       = pack_bf16x4(v0, sc);
            o2[t + 256] = pack_bf16x4(v1, sc);
            o2[t + 512] = pack_bf16x4(v2, sc);
            o2[t + 768] = pack_bf16x4(v3, sc);
            __syncthreads();
        }
        const size_t n4 = (size_t)OUTDIM * INDIM / 4;
        const float4* w4 = reinterpret_cast<const float4*>(W);
        uint2* o2 = reinterpret_cast<uint2*>(g_wb);
        size_t stride = (size_t)GBLK * 256;
        for (size_t i = (size_t)blockIdx.x * 256 + t; i < n4; i += stride) {
            float4 v = w4[i];
            o2[i] = pack_bf16x4(v, 1.0f);
        }
    }

    // ---- grid barrier (all 296 CTAs co-resident; counter reset by K1) ----
    __threadfence();
    __syncthreads();
    if (t == 0) {
        atomicAdd(&g_bar, 1u);
        while (*(volatile unsigned int*)&g_bar < (unsigned)GBLK) { }
    }
    __syncthreads();
    __threadfence();

    // ---- phase 2: persistent GEMM + spike epilogue (2-stage pipeline) ----
    const int warp_m = wid >> 2, warp_n = wid & 3;
    const int lrow = t >> 1, lhalf = (t & 1) * 4;
    const int a_row = warp_m * 64 + (lane & 15);
    const int a_csel = lane >> 4;
    const int b_row = warp_n * 32 + (lane & 7) + ((lane >> 4) << 3);
    const int b_csel = (lane >> 3) & 1;

    for (int tile = blockIdx.x; tile < NTILES; tile += GBLK) {
        const int NUM_N = OUTDIM / BN;    // 32
        const int GROUP = 8;
        int per_g = GROUP * NUM_N;
        int g = tile / per_g;
        int rem = tile - g * per_g;
        const size_t m0 = (size_t)(g * GROUP + (rem & (GROUP - 1))) * BM;
        const size_t n0 = (size_t)(rem / GROUP) * BN;

        auto load_stage = [&](int it) {
            uint32_t base = smem_base + (uint32_t)(it % NSTAGES) * STAGE_BYTES;
            const char* as = (const char*)(g_xb + (m0 + (size_t)lrow) * INDIM
                                           + (size_t)it * BK) + lhalf * 16;
            const char* bs = (const char*)(g_wb + (n0 + (size_t)lrow) * INDIM
                                           + (size_t)it * BK) + lhalf * 16;
            #pragma unroll
            for (int c = 0; c < 4; c++) {
                CPA16(base + sw_off(lrow, lhalf + c), as + c * 16);
                CPA16(base + TILE_BYTES + sw_off(lrow, lhalf + c), bs + c * 16);
            }
        };

        load_stage(0); asm volatile("cp.async.commit_group;");
        load_stage(1); asm volatile("cp.async.commit_group;");

        float acc[4][4][4];
        #pragma unroll
        for (int i = 0; i < 4; i++)
            #pragma unroll
            for (int j = 0; j < 4; j++)
                #pragma unroll
                for (int q = 0; q < 4; q++) acc[i][j][q] = 0.0f;

        for (int i = 0; i < NKITERS; i++) {
            // stage i resident (<=1 group pending = stage i+1)
            asm volatile("cp.async.wait_group 1;");
            __syncthreads();

            uint32_t abase = smem_base + (uint32_t)(i % NSTAGES) * STAGE_BYTES;
            uint32_t bbase = abase + TILE_BYTES;

            #pragma unroll
            for (int ks = 0; ks < 4; ks++) {
                const int kc = ks * 2;
                uint32_t a[4][4];
                #pragma unroll
                for (int mf = 0; mf < 4; mf++) {
                    int r = a_row + mf * 16;
                    ldsm_x4(a[mf][0], a[mf][1], a[mf][2], a[mf][3],
                            abase + sw_off(r, kc + a_csel));
                }
                uint32_t b[2][4];
                #pragma unroll
                for (int bf = 0; bf < 2; bf++) {
                    int r = b_row + bf * 16;
                    ldsm_x4(b[bf][0], b[bf][1], b[bf][2], b[bf][3],
                            bbase + sw_off(r, kc + b_csel));
                }
                #pragma unroll
                for (int mf = 0; mf < 4; mf++) {
                    #pragma unroll
                    for (int bf = 0; bf < 2; bf++) {
                        mma16816(acc[mf][bf * 2 + 0], a[mf], b[bf][0], b[bf][1]);
                        mma16816(acc[mf][bf * 2 + 1], a[mf], b[bf][2], b[bf][3]);
                    }
                }
            }
            // all threads done reading buffer i%2 before it is refilled
            __syncthreads();
            if (i + 2 < NKITERS) {
                load_stage(i + 2);
                asm volatile("cp.async.commit_group;");
            }
        }

        #pragma unroll
        for (int mf = 0; mf < 4; mf++) {
            size_t row = m0 + (size_t)(warp_m * 64 + mf * 16 + (lane >> 2));
            #pragma unroll
            for (int nf = 0; nf < 4; nf++) {
                size_t col = n0 + (size_t)(warp_n * 32 + nf * 8 + (lane & 3) * 2);
                float2 v0, v1;
                v0.x = (acc[mf][nf][0] >= 1.0f) ? 1.0f : 0.0f;
                v0.y = (acc[mf][nf][1] >= 1.0f) ? 1.0f : 0.0f;
                v1.x = (acc[mf][nf][2] >= 1.0f) ? 1.0f : 0.0f;
                v1.y = (acc[mf][nf][3] >= 1.0f) ? 1.0f : 0.0f;
                *reinterpret_cast<float2*>(out + row * OUTDIM + col) = v0;
                *reinterpret_cast<float2*>(out + (row + 8) * OUTDIM + col) = v1;
            }
        }
        __syncthreads();
    }
}

// ---------------------------------------------------------------------------
// Launch: 2 static launches; behavior a pure function of inputs.
// ---------------------------------------------------------------------------
extern "C" void kernel_launch(void* const* d_in, const int* in_sizes, int n_in,
                              void* d_out, int out_size) {
    const float* x = (const float*)d_in[0];
    const float* W = (const float*)d_in[1];
    float* out = (float*)d_out;

    cudaFuncSetAttribute(fallback_kernel,
                         cudaFuncAttributeMaxDynamicSharedMemorySize, SMEM_DYN);

    check_zero_kernel<<<NB1, 256>>>(W, out);               // cert + zero-fill
    fallback_kernel<<<GBLK, 256, SMEM_DYN>>>(x, W, out);   // fallback only
}